// round 11
// baseline (speedup 1.0000x reference)
#include <cuda_runtime.h>
#include <cstdint>
#include <math.h>

#define COL 14
#define NJ 23
#define PAIR_ELEMS (COL * COL)   // 196
#define WARPS_PER_BLOCK 8
#define BLOCK_THREADS (WARPS_PER_BLOCK * 32)
#define CHUNK 10                 // 94208/(8*10) -> 1178 blocks ~ one wave

__device__ float        g_sum   = 0.0f;
__device__ unsigned int g_count = 0u;

// gaussian weights exp(-k^2/2)/sum, k=-4..4 (normalized in double, cast to f32)
__device__ __constant__ float c_w[9] = {
    0.000133832f, 0.00443186f, 0.05399111f, 0.24197140f, 0.39894345f,
    0.24197140f, 0.05399111f, 0.00443186f, 0.000133832f
};

__device__ __forceinline__ void amax_node(float& v, int& i, float vr, int ir) {
    if (vr > v) { v = vr; i = ir; }   // strict >: ties keep smaller index
}

__device__ __forceinline__ void cp_async16(unsigned int dst_smem, const void* src) {
    asm volatile("cp.async.cg.shared.global [%0], [%1], 16;\n"
                 :: "r"(dst_smem), "l"(src));
}
#define CP_COMMIT() asm volatile("cp.async.commit_group;\n" ::)
#define CP_WAIT1()  asm volatile("cp.async.wait_group 1;\n" ::)

__global__ __launch_bounds__(BLOCK_THREADS, 8)
void mse3d_kernel(const float* __restrict__ o,
                  const float* __restrict__ h,
                  const float* __restrict__ t,
                  const int*   __restrict__ v,
                  float* __restrict__ out,
                  int n_pairs, int nblocks) {
    // sMt[i*COL + r] = M[r][i]  (column i of M contiguous)
    __shared__ float sMt[PAIR_ELEMS];
    __shared__ float sColMin[COL], sColMax[COL];
    __shared__ float sColS1[COL], sColS2[COL];
    __shared__ float wsum[WARPS_PER_BLOCK];
    // double-buffered h tiles, one region per warp (50 float4 = padded to 800B)
    __shared__ float4 sbuf[WARPS_PER_BLOCK][2][50];

    const int tid = threadIdx.x;

    // ---- per-block gaussian matrix build ----
    if (tid < PAIR_ELEMS) {
        const int outr = tid / COL;
        const int i    = tid % COL;
        float m = 0.0f;
        #pragma unroll
        for (int k = -4; k <= 4; k++) {
            int ii = (outr + k + 2 * COL) % (2 * COL);
            if (ii >= COL) ii = 2 * COL - 1 - ii;
            if (ii == i) m += c_w[k + 4];
        }
        sMt[i * COL + outr] = m;
    }
    __syncthreads();
    if (tid < COL) {
        float mn = INFINITY, mx = -INFINITY, s1 = 0.0f, s2 = 0.0f;
        #pragma unroll
        for (int r = 0; r < COL; r++) {
            float val = sMt[tid * COL + r];   // M[r][tid]
            mn = fminf(mn, val);
            mx = fmaxf(mx, val);
            s1 += val;
            s2 = fmaf(val, val, s2);
        }
        sColMin[tid] = mn;
        sColMax[tid] = mx;
        sColS1[tid]  = s1;
        sColS2[tid]  = s2;
    }
    __syncthreads();

    const int lane  = tid & 31;
    const int warp  = tid >> 5;
    const int gwarp = blockIdx.x * WARPS_PER_BLOCK + warp;
    const int pair0 = gwarp * CHUNK;
    const int cnt   = min(CHUNK, n_pairs - pair0);

    float acc  = 0.0f;   // d1
    float acc2 = 0.0f;   // d2 + per-pair constant terms

    if (cnt > 0) {
        const bool hasb = (lane < 17);        // second float4 (idx 32+lane < 49)

        // per-lane element coordinates, loop-invariant
        const int ea = 4 * lane;
        const int ra0 = ea / COL, ca0 = ea - ra0 * COL;
        const int eb = 4 * (32 + lane);
        const int rb0 = eb / COL, cb0 = eb - rb0 * COL;

        const float4* hbase = (const float4*)(h + (size_t)pair0 * PAIR_ELEMS);
        const unsigned int sb =
            (unsigned int)__cvta_generic_to_shared(&sbuf[warp][0][0]);

        // ---- per-chunk t/v prefetch (coalesced), broadcast via shuffle ----
        const float tl = (lane < 3 * cnt) ? t[(size_t)pair0 * 3 + lane] : 0.0f;
        const int   vl = (lane < cnt) ? v[(size_t)(pair0 + lane) * 2] : 0;

        // ---- prologue: fill both stages ----
        {
            const float4* src0 = hbase + lane;
            cp_async16(sb + lane * 16, src0);
            if (hasb) cp_async16(sb + (32 + lane) * 16, src0 + 32);
        }
        CP_COMMIT();
        if (cnt > 1) {
            const float4* src1 = hbase + 49 + lane;
            cp_async16(sb + (50 + lane) * 16, src1);
            if (hasb) cp_async16(sb + (50 + 32 + lane) * 16, src1 + 32);
        }
        CP_COMMIT();

        int myAmax = 0;   // lane k banks pair k's argmax

        // ================= Phase 1: h-only (d1 + argmax) =================
        for (int k = 0; k < cnt; k++) {
            const int st = k & 1;

            CP_WAIT1();
            __syncwarp();
            float4 va = sbuf[warp][st][lane];
            float4 vb = hasb ? sbuf[warp][st][32 + lane]
                             : make_float4(0.f, 0.f, 0.f, 0.f);
            __syncwarp();   // all reads done before refilling this stage

            // refill this stage with pair k+2 (async, consumed 2 rounds later)
            if (k + 2 < cnt) {
                const float4* srcn = hbase + (size_t)(k + 2) * 49 + lane;
                const unsigned int dstn = sb + (st * 50 + lane) * 16;
                cp_async16(dstn, srcn);
                if (hasb) cp_async16(dstn + 32 * 16, srcn + 32);
            }
            CP_COMMIT();

            // per-pair scalars via shuffle (no memory)
            const float t0 = __shfl_sync(0xffffffffu, tl, 3 * k);
            const float t1 = __shfl_sync(0xffffffffu, tl, 3 * k + 1);
            const int   vv = __shfl_sync(0xffffffffu, vl, k);

            // ---- tree argmax over the 8 local elements ----
            float m0 = va.x; int i0 = ea;
            amax_node(m0, i0, va.y, ea + 1);
            float m1 = va.z; int i1 = ea + 2;
            amax_node(m1, i1, va.w, ea + 3);
            float m2 = vb.x; int i2 = eb;
            amax_node(m2, i2, vb.y, eb + 1);
            float m3 = vb.z; int i3 = eb + 2;
            amax_node(m3, i3, vb.w, eb + 3);
            amax_node(m0, i0, m1, i1);
            amax_node(m2, i2, m3, i3);
            amax_node(m0, i0, m2, i2);
            // h >= 0: bits order-isomorphic; first occurrence via min-index
            const unsigned int bbits = __float_as_uint(m0);
            const unsigned int mbits = __reduce_max_sync(0xffffffffu, bbits);
            const int amax = (int)__reduce_min_sync(
                0xffffffffu, (bbits == mbits) ? (unsigned)i0 : 0xffffffffu);
            if (lane == k) myAmax = amax;   // bank for phase 2

            // ---- always: sum h^2 ----
            acc = fmaf(va.x, va.x, acc);
            acc = fmaf(va.y, va.y, acc);
            acc = fmaf(va.z, va.z, acc);
            acc = fmaf(va.w, va.w, acc);
            acc = fmaf(vb.x, vb.x, acc);
            acc = fmaf(vb.y, vb.y, acc);
            acc = fmaf(vb.z, vb.z, acc);
            acc = fmaf(vb.w, vb.w, acc);

            // ---- mask / normalization ----
            const int xi = (int)truncf(t0 * (float)COL);
            const int yi = (int)truncf(t1 * (float)COL);
            const bool in_range = (xi >= 0) && (xi <= COL - 1) &&
                                  (yi >= 0) && (yi <= COL - 1);
            const bool mask = (vv == 1) && in_range;

            if (mask) {
                // d1_pair = sum h^2 - 2*sum(h*tt) + sum(tt^2)
                const int xc = min(max(xi, 0), COL - 1);
                const int yc = min(max(yi, 0), COL - 1);
                const float mn  = sColMin[yc] * sColMin[xc];
                const float mx  = sColMax[yc] * sColMax[xc];
                const float inv = 1.0f / (mx - mn);
                const float nb  = -mn * inv;
                const float* gy = &sMt[yc * COL];
                const float* gx = &sMt[xc * COL];

                float hw = 0.0f, sh = 0.0f;
                {
                    int r = ra0, c = ca0;
                    float hv[4] = {va.x, va.y, va.z, va.w};
                    #pragma unroll
                    for (int q = 0; q < 4; q++) {
                        hw = fmaf(hv[q], gy[r] * gx[c], hw);
                        sh += hv[q];
                        if (++c == COL) { c = 0; ++r; }
                    }
                }
                if (hasb) {
                    int r = rb0, c = cb0;
                    float hv[4] = {vb.x, vb.y, vb.z, vb.w};
                    #pragma unroll
                    for (int q = 0; q < 4; q++) {
                        hw = fmaf(hv[q], gy[r] * gx[c], hw);
                        sh += hv[q];
                        if (++c == COL) { c = 0; ++r; }
                    }
                }
                acc = fmaf(-2.0f * inv, hw, acc);
                acc = fmaf(-2.0f * nb,  sh, acc);
                if (lane == 0) {
                    const float S1 = sColS1[yc] * sColS1[xc];
                    const float S2 = sColS2[yc] * sColS2[xc];
                    float ct = inv * inv * S2;
                    ct = fmaf(2.0f * inv * nb, S1, ct);
                    ct = fmaf((float)PAIR_ELEMS * nb, nb, ct);
                    acc2 += ct;
                }
            }
        }

        // ====== Phase 2: all o-gathers at once (up to 30 concurrent) ======
        {
            const int kq = min(lane / 3, cnt - 1);     // clamped for shfl
            const int am = __shfl_sync(0xffffffffu, myAmax, kq);
            if (lane < 3 * cnt) {
                const int k    = lane / 3;
                const int comp = lane - 3 * k;
                const int pair = pair0 + k;
                const int b    = pair / NJ;
                const int j    = pair - b * NJ;
                const int ayk  = am / COL;
                const int axk  = am - ayk * COL;
                const int row  = b * (3 * NJ) + j + comp * NJ;
                const float ov = __ldg(o + ((size_t)row * PAIR_ELEMS + am));
                const float scale = 1.0f / (float)COL;
                const float addv = (comp == 0) ? (float)axk * scale
                                 : ((comp == 1) ? (float)ayk * scale : 0.0f);
                const float d = ov + addv - tl;        // tl == t[pair*3+comp]
                acc2 = fmaf(d, d, acc2);
            }
        }
    }

    acc += acc2;

    // ---- block reduction ----
    #pragma unroll
    for (int off = 16; off > 0; off >>= 1)
        acc += __shfl_down_sync(0xffffffffu, acc, off);
    if (lane == 0) wsum[warp] = acc;
    __syncthreads();

    if (warp == 0) {
        float s = (lane < WARPS_PER_BLOCK) ? wsum[lane] : 0.0f;
        #pragma unroll
        for (int off = WARPS_PER_BLOCK / 2; off > 0; off >>= 1)
            s += __shfl_down_sync(0xffffffffu, s, off);
        if (lane == 0) {
            atomicAdd(&g_sum, s * (1.0f / (float)NJ));
            __threadfence();
            unsigned int done = atomicAdd(&g_count, 1u);
            if (done == (unsigned)nblocks - 1) {
                float total = atomicExch(&g_sum, 0.0f);
                out[0] = total;
                g_count = 0u;
                __threadfence();
            }
        }
    }
}

extern "C" void kernel_launch(void* const* d_in, const int* in_sizes, int n_in,
                              void* d_out, int out_size) {
    const float* o = (const float*)d_in[0];
    const float* h = (const float*)d_in[1];
    const float* t = (const float*)d_in[2];
    const int*   v = (const int*)d_in[3];
    float* out = (float*)d_out;

    const int n_pairs = in_sizes[1] / PAIR_ELEMS;   // B * NJ from h
    const int pairs_per_block = WARPS_PER_BLOCK * CHUNK;
    const int blocks = (n_pairs + pairs_per_block - 1) / pairs_per_block;

    mse3d_kernel<<<blocks, BLOCK_THREADS>>>(o, h, t, v, out, n_pairs, blocks);
}

// round 12
// speedup vs baseline: 1.1464x; 1.1464x over previous
#include <cuda_runtime.h>
#include <cstdint>
#include <math.h>

#define COL 14
#define NJ 23
#define PAIR_ELEMS (COL * COL)   // 196
#define WARPS_PER_BLOCK 8
#define BLOCK_THREADS (WARPS_PER_BLOCK * 32)
#define CHUNK 10                 // 94208/(8*10) -> 1178 blocks ~ one wave

__device__ float        g_sum   = 0.0f;
__device__ unsigned int g_count = 0u;

// gaussian weights exp(-k^2/2)/sum, k=-4..4 (normalized in double, cast to f32)
__device__ __constant__ float c_w[9] = {
    0.000133832f, 0.00443186f, 0.05399111f, 0.24197140f, 0.39894345f,
    0.24197140f, 0.05399111f, 0.00443186f, 0.000133832f
};

__device__ __forceinline__ void amax_node(float& v, int& i, float vr, int ir) {
    if (vr > v) { v = vr; i = ir; }   // strict >: ties keep smaller index
}

__device__ __forceinline__ void prefetch_l1(const void* p) {
    asm volatile("prefetch.global.L1 [%0];" :: "l"(p));
}

__global__ __launch_bounds__(BLOCK_THREADS, 8)
void mse3d_kernel(const float* __restrict__ o,
                  const float* __restrict__ h,
                  const float* __restrict__ t,
                  const int*   __restrict__ v,
                  float* __restrict__ out,
                  int n_pairs, int nblocks) {
    // sMt[i*COL + r] = M[r][i]  (column i of M contiguous)
    __shared__ float sMt[PAIR_ELEMS];
    __shared__ float sColMin[COL], sColMax[COL];
    __shared__ float sColS1[COL], sColS2[COL];
    __shared__ float wsum[WARPS_PER_BLOCK];

    const int tid = threadIdx.x;

    // ---- per-block gaussian matrix build ----
    if (tid < PAIR_ELEMS) {
        const int outr = tid / COL;
        const int i    = tid % COL;
        float m = 0.0f;
        #pragma unroll
        for (int k = -4; k <= 4; k++) {
            int ii = (outr + k + 2 * COL) % (2 * COL);
            if (ii >= COL) ii = 2 * COL - 1 - ii;
            if (ii == i) m += c_w[k + 4];
        }
        sMt[i * COL + outr] = m;
    }
    __syncthreads();
    if (tid < COL) {
        float mn = INFINITY, mx = -INFINITY, s1 = 0.0f, s2 = 0.0f;
        #pragma unroll
        for (int r = 0; r < COL; r++) {
            float val = sMt[tid * COL + r];   // M[r][tid]
            mn = fminf(mn, val);
            mx = fmaxf(mx, val);
            s1 += val;
            s2 = fmaf(val, val, s2);
        }
        sColMin[tid] = mn;
        sColMax[tid] = mx;
        sColS1[tid]  = s1;
        sColS2[tid]  = s2;
    }
    __syncthreads();

    const int lane  = tid & 31;
    const int warp  = tid >> 5;
    const int gwarp = blockIdx.x * WARPS_PER_BLOCK + warp;
    const int pair0 = gwarp * CHUNK;
    const int cnt   = min(CHUNK, n_pairs - pair0);

    float acc  = 0.0f;   // d1
    float acc2 = 0.0f;   // d2 + per-pair constant terms

    if (cnt > 0) {
        const bool hasb = (lane < 17);        // second float4 (idx 32+lane < 49)

        // per-lane element coordinates, loop-invariant
        const int ea = 4 * lane;
        const int ra0 = ea / COL, ca0 = ea - ra0 * COL;
        const int eb = 4 * (32 + lane);
        const int rb0 = eb / COL, cb0 = eb - rb0 * COL;

        const float4* hbase = (const float4*)(h + (size_t)pair0 * PAIR_ELEMS);

        // ---- per-chunk t/v prefetch (coalesced), broadcast via shuffle ----
        const float tl = (lane < 3 * cnt) ? t[(size_t)pair0 * 3 + lane] : 0.0f;
        const int   vl = (lane < cnt) ? v[(size_t)(pair0 + lane) * 2] : 0;

        // warm L1 for pair 0
        prefetch_l1(hbase + lane);
        if (hasb) prefetch_l1(hbase + 32 + lane);

        int myAmax = 0;   // lane k banks pair k's argmax

        // ================= Phase 1: h-only (d1 + argmax) =================
        for (int k = 0; k < cnt; k++) {
            const float4* hp = hbase + (size_t)k * 49;
            float4 va = hp[lane];
            float4 vb = hasb ? hp[32 + lane] : make_float4(0.f, 0.f, 0.f, 0.f);

            // prefetch next pair's tile into L1 (zero-register pipelining)
            if (k + 1 < cnt) {
                prefetch_l1(hp + 49 + lane);
                if (hasb) prefetch_l1(hp + 49 + 32 + lane);
            }

            // per-pair scalars via shuffle (no memory)
            const float t0 = __shfl_sync(0xffffffffu, tl, 3 * k);
            const float t1 = __shfl_sync(0xffffffffu, tl, 3 * k + 1);
            const int   vv = __shfl_sync(0xffffffffu, vl, k);

            // ---- tree argmax over the 8 local elements ----
            float m0 = va.x; int i0 = ea;
            amax_node(m0, i0, va.y, ea + 1);
            float m1 = va.z; int i1 = ea + 2;
            amax_node(m1, i1, va.w, ea + 3);
            float m2 = vb.x; int i2 = eb;
            amax_node(m2, i2, vb.y, eb + 1);
            float m3 = vb.z; int i3 = eb + 2;
            amax_node(m3, i3, vb.w, eb + 3);
            amax_node(m0, i0, m1, i1);
            amax_node(m2, i2, m3, i3);
            amax_node(m0, i0, m2, i2);
            // h >= 0: bits order-isomorphic; first occurrence via min-index
            const unsigned int bbits = __float_as_uint(m0);
            const unsigned int mbits = __reduce_max_sync(0xffffffffu, bbits);
            const int amax = (int)__reduce_min_sync(
                0xffffffffu, (bbits == mbits) ? (unsigned)i0 : 0xffffffffu);
            if (lane == k) myAmax = amax;   // bank for phase 2

            // ---- always: sum h^2 ----
            acc = fmaf(va.x, va.x, acc);
            acc = fmaf(va.y, va.y, acc);
            acc = fmaf(va.z, va.z, acc);
            acc = fmaf(va.w, va.w, acc);
            acc = fmaf(vb.x, vb.x, acc);
            acc = fmaf(vb.y, vb.y, acc);
            acc = fmaf(vb.z, vb.z, acc);
            acc = fmaf(vb.w, vb.w, acc);

            // ---- mask / normalization ----
            const int xi = (int)truncf(t0 * (float)COL);
            const int yi = (int)truncf(t1 * (float)COL);
            const bool in_range = (xi >= 0) && (xi <= COL - 1) &&
                                  (yi >= 0) && (yi <= COL - 1);
            const bool mask = (vv == 1) && in_range;

            if (mask) {
                // d1_pair = sum h^2 - 2*sum(h*tt) + sum(tt^2)
                const int xc = min(max(xi, 0), COL - 1);
                const int yc = min(max(yi, 0), COL - 1);
                const float mn  = sColMin[yc] * sColMin[xc];
                const float mx  = sColMax[yc] * sColMax[xc];
                const float inv = 1.0f / (mx - mn);
                const float nb  = -mn * inv;
                const float* gy = &sMt[yc * COL];
                const float* gx = &sMt[xc * COL];

                float hw = 0.0f, sh = 0.0f;
                {
                    int r = ra0, c = ca0;
                    float hv[4] = {va.x, va.y, va.z, va.w};
                    #pragma unroll
                    for (int q = 0; q < 4; q++) {
                        hw = fmaf(hv[q], gy[r] * gx[c], hw);
                        sh += hv[q];
                        if (++c == COL) { c = 0; ++r; }
                    }
                }
                if (hasb) {
                    int r = rb0, c = cb0;
                    float hv[4] = {vb.x, vb.y, vb.z, vb.w};
                    #pragma unroll
                    for (int q = 0; q < 4; q++) {
                        hw = fmaf(hv[q], gy[r] * gx[c], hw);
                        sh += hv[q];
                        if (++c == COL) { c = 0; ++r; }
                    }
                }
                acc = fmaf(-2.0f * inv, hw, acc);
                acc = fmaf(-2.0f * nb,  sh, acc);
                if (lane == 0) {
                    const float S1 = sColS1[yc] * sColS1[xc];
                    const float S2 = sColS2[yc] * sColS2[xc];
                    float ct = inv * inv * S2;
                    ct = fmaf(2.0f * inv * nb, S1, ct);
                    ct = fmaf((float)PAIR_ELEMS * nb, nb, ct);
                    acc2 += ct;
                }
            }
        }

        // ====== Phase 2: all o-gathers at once (up to 30 concurrent) ======
        {
            const int kq = min(lane / 3, cnt - 1);     // clamped for shfl
            const int am = __shfl_sync(0xffffffffu, myAmax, kq);
            if (lane < 3 * cnt) {
                const int k    = lane / 3;
                const int comp = lane - 3 * k;
                const int pair = pair0 + k;
                const int b    = pair / NJ;
                const int j    = pair - b * NJ;
                const int ayk  = am / COL;
                const int axk  = am - ayk * COL;
                const int row  = b * (3 * NJ) + j + comp * NJ;
                const float ov = __ldg(o + ((size_t)row * PAIR_ELEMS + am));
                const float scale = 1.0f / (float)COL;
                const float addv = (comp == 0) ? (float)axk * scale
                                 : ((comp == 1) ? (float)ayk * scale : 0.0f);
                const float d = ov + addv - tl;        // tl == t[pair*3+comp]
                acc2 = fmaf(d, d, acc2);
            }
        }
    }

    acc += acc2;

    // ---- block reduction ----
    #pragma unroll
    for (int off = 16; off > 0; off >>= 1)
        acc += __shfl_down_sync(0xffffffffu, acc, off);
    if (lane == 0) wsum[warp] = acc;
    __syncthreads();

    if (warp == 0) {
        float s = (lane < WARPS_PER_BLOCK) ? wsum[lane] : 0.0f;
        #pragma unroll
        for (int off = WARPS_PER_BLOCK / 2; off > 0; off >>= 1)
            s += __shfl_down_sync(0xffffffffu, s, off);
        if (lane == 0) {
            atomicAdd(&g_sum, s * (1.0f / (float)NJ));
            __threadfence();
            unsigned int done = atomicAdd(&g_count, 1u);
            if (done == (unsigned)nblocks - 1) {
                float total = atomicExch(&g_sum, 0.0f);
                out[0] = total;
                g_count = 0u;
                __threadfence();
            }
        }
    }
}

extern "C" void kernel_launch(void* const* d_in, const int* in_sizes, int n_in,
                              void* d_out, int out_size) {
    const float* o = (const float*)d_in[0];
    const float* h = (const float*)d_in[1];
    const float* t = (const float*)d_in[2];
    const int*   v = (const int*)d_in[3];
    float* out = (float*)d_out;

    const int n_pairs = in_sizes[1] / PAIR_ELEMS;   // B * NJ from h
    const int pairs_per_block = WARPS_PER_BLOCK * CHUNK;
    const int blocks = (n_pairs + pairs_per_block - 1) / pairs_per_block;

    mse3d_kernel<<<blocks, BLOCK_THREADS>>>(o, h, t, v, out, n_pairs, blocks);
}